// round 1
// baseline (speedup 1.0000x reference)
#include <cuda_runtime.h>
#include <cuda_bf16.h>
#include <math.h>

// ---------------- problem constants ----------------
#define S      15
#define BATCH  32
#define NNODE  5000
#define NEDGE  80000
#define NEDGE_SL (NEDGE + NNODE)   // with self loops = 85000
#define FIN    16
#define HID    512
#define G3     1536                // 3*HID
#define SB     (S*BATCH)           // 480
#define K5     5000

// ---------------- device scratch (no allocs allowed) ----------------
struct __align__(8) Edge { int s; float w; };

__device__ int   g_indeg[NNODE];
__device__ int   g_off[NNODE + 1];
__device__ int   g_pos[NNODE];
__device__ float g_dinv[NNODE];
__device__ Edge  g_edges[NEDGE_SL];
__device__ int   g_is64;

__device__ float g_g[SB * NNODE];       // GCN output, [480][5000]
__device__ float g_gi0[SB * G3];        // precomputed layer-0 input gates
__device__ float g_gi1[2][BATCH * G3];  // double-buffered layer-1 input gates
__device__ float g_out1[S * BATCH * HID];
__device__ float g_h0[2][BATCH * HID];
__device__ float g_h1[2][BATCH * HID];

// ---------------- packed f32x2 helpers ----------------
#define FFMA2(c, a, b) asm("fma.rn.f32x2 %0, %1, %2, %0;" : "+l"(c) : "l"(a), "l"(b))

__device__ __forceinline__ float hsum2(unsigned long long v) {
    float lo, hi;
    asm("mov.b64 {%0,%1}, %2;" : "=f"(lo), "=f"(hi) : "l"(v));
    return lo + hi;
}

// ---------------- prep kernels ----------------
__global__ void init_kernel(const int* __restrict__ ei) {
    int i = blockIdx.x * blockDim.x + threadIdx.x;
    if (i < NNODE) g_indeg[i] = 1;                 // self loop
    if (i < BATCH * HID) { g_h0[0][i] = 0.f; g_h1[0][i] = 0.f; }
    if (i == 0) {
        // detect whether edge_index is int64 (high words all zero) or int32
        int f = 1;
        for (int q = 0; q < 64; q++) if (ei[2 * q + 1] != 0) { f = 0; break; }
        g_is64 = f;
    }
}

__global__ void count_kernel(const int* __restrict__ ei) {
    int e = blockIdx.x * blockDim.x + threadIdx.x;
    if (e >= NEDGE) return;
    int is64 = g_is64;
    int t = is64 ? ei[2 * (NEDGE + e)] : ei[NEDGE + e];
    atomicAdd(&g_indeg[t], 1);
}

__global__ void scan_kernel() {
    __shared__ int ssum[1024];
    int t = threadIdx.x;
    int vals[5];
    int s = 0;
    #pragma unroll
    for (int q = 0; q < 5; q++) {
        int idx = t * 5 + q;
        vals[q] = (idx < NNODE) ? g_indeg[idx] : 0;
        s += vals[q];
    }
    ssum[t] = s;
    __syncthreads();
    for (int off = 1; off < 1024; off <<= 1) {
        int v = (t >= off) ? ssum[t - off] : 0;
        __syncthreads();
        ssum[t] += v;
        __syncthreads();
    }
    int run = ssum[t] - s;  // exclusive prefix
    #pragma unroll
    for (int q = 0; q < 5; q++) {
        int idx = t * 5 + q;
        if (idx < NNODE) {
            g_off[idx] = run;
            g_pos[idx] = run;
            g_dinv[idx] = rsqrtf((float)vals[q]);
            run += vals[q];
        }
    }
    if (t == 1023) g_off[NNODE] = ssum[1023];
}

__global__ void fill_kernel(const int* __restrict__ ei) {
    int e = blockIdx.x * blockDim.x + threadIdx.x;
    if (e >= NEDGE_SL) return;
    int is64 = g_is64;
    int s, t;
    if (e < NEDGE) {
        s = is64 ? ei[2 * e] : ei[e];
        t = is64 ? ei[2 * (NEDGE + e)] : ei[NEDGE + e];
    } else {
        s = t = e - NEDGE;
    }
    int idx = atomicAdd(&g_pos[t], 1);
    Edge E; E.s = s; E.w = g_dinv[s] * g_dinv[t];
    g_edges[idx] = E;
}

// ---------------- fused GCN (one CTA per (s,b) slice) ----------------
// smem: hA[10000], hB[10000]  = 80000 bytes
__global__ void gcn_kernel(const float* __restrict__ x, const float* __restrict__ W1,
                           const float* __restrict__ b1, const float* __restrict__ W2,
                           const float* __restrict__ b2) {
    extern __shared__ float sm[];
    float* hA = sm;
    float* hB = sm + 2 * NNODE;
    int sb = blockIdx.x;
    int s = sb >> 5;
    int tid = threadIdx.x;

    float w10[FIN], w11[FIN];
    #pragma unroll
    for (int f = 0; f < FIN; f++) {
        w10[f] = W1[s * (FIN * 2) + f * 2 + 0];
        w11[f] = W1[s * (FIN * 2) + f * 2 + 1];
    }
    float b10 = b1[s * 2 + 0], b11 = b1[s * 2 + 1];
    float w20 = W2[s * 2 + 0], w21 = W2[s * 2 + 1];
    float b2s = b2[s];

    const float* xb = x + (size_t)sb * NNODE * FIN;
    // linear: h = x @ W1  -> hA[n][0..1]
    for (int n = tid; n < NNODE; n += 512) {
        const float4* xp = (const float4*)(xb + (size_t)n * FIN);
        float xv[16];
        *(float4*)&xv[0]  = xp[0];
        *(float4*)&xv[4]  = xp[1];
        *(float4*)&xv[8]  = xp[2];
        *(float4*)&xv[12] = xp[3];
        float a0 = 0.f, a1 = 0.f;
        #pragma unroll
        for (int f = 0; f < FIN; f++) { a0 += xv[f] * w10[f]; a1 += xv[f] * w11[f]; }
        hA[2 * n] = a0; hA[2 * n + 1] = a1;
    }
    __syncthreads();
    // propagate 1 + bias + relu -> hB
    for (int n = tid; n < NNODE; n += 512) {
        int e0 = g_off[n], e1 = g_off[n + 1];
        float a0 = 0.f, a1 = 0.f;
        for (int e = e0; e < e1; e++) {
            Edge E = g_edges[e];
            a0 += E.w * hA[2 * E.s];
            a1 += E.w * hA[2 * E.s + 1];
        }
        hB[2 * n]     = fmaxf(a0 + b10, 0.f);
        hB[2 * n + 1] = fmaxf(a1 + b11, 0.f);
    }
    __syncthreads();
    // linear 2 -> hA[n]
    for (int n = tid; n < NNODE; n += 512)
        hA[n] = hB[2 * n] * w20 + hB[2 * n + 1] * w21;
    __syncthreads();
    // propagate 2 + bias + tanh -> g_g
    float* gout = g_g + (size_t)sb * NNODE;
    for (int n = tid; n < NNODE; n += 512) {
        int e0 = g_off[n], e1 = g_off[n + 1];
        float q = 0.f;
        for (int e = e0; e < e1; e++) {
            Edge E = g_edges[e];
            q += E.w * hA[E.s];
        }
        gout[n] = tanhf(q + b2s);
    }
}

// ---------------- gi0 = g @ w_ih0^T + b_ih0  (fp32x2 tiled GEMM) ----------------
#define BM 48
#define BN 96
#define KC 16
#define NCH ((K5 + KC - 1) / KC)   // 313

__global__ __launch_bounds__(256) void gemm_gi0_kernel(const float* __restrict__ wih0,
                                                       const float* __restrict__ bih0) {
    __shared__ __align__(16) float a_sm[BM * 18];
    __shared__ __align__(16) float b_sm[BN * 18];
    int tid = threadIdx.x;
    int m0 = blockIdx.x * BM;
    int n0 = blockIdx.y * BN;
    int tx = tid & 15, ty = tid >> 4;

    unsigned long long acc[3][6];
    #pragma unroll
    for (int i = 0; i < 3; i++)
        #pragma unroll
        for (int j = 0; j < 6; j++) acc[i][j] = 0ull;

    int ra[3], ka[3], rb[6], kb[6];
    #pragma unroll
    for (int i = 0; i < 3; i++) { int e = tid + i * 256; ra[i] = e >> 4; ka[i] = e & 15; }
    #pragma unroll
    for (int i = 0; i < 6; i++) { int e = tid + i * 256; rb[i] = e >> 4; kb[i] = e & 15; }

    float pa[3], pb[6];
    // prefetch chunk 0
    #pragma unroll
    for (int i = 0; i < 3; i++) pa[i] = g_g[(size_t)(m0 + ra[i]) * K5 + ka[i]];
    #pragma unroll
    for (int i = 0; i < 6; i++) pb[i] = wih0[(size_t)(n0 + rb[i]) * K5 + kb[i]];

    for (int c = 0; c < NCH; c++) {
        #pragma unroll
        for (int i = 0; i < 3; i++) a_sm[ra[i] * 18 + ka[i]] = pa[i];
        #pragma unroll
        for (int i = 0; i < 6; i++) b_sm[rb[i] * 18 + kb[i]] = pb[i];
        __syncthreads();
        int k0n = (c + 1) * KC;
        if (c + 1 < NCH) {
            #pragma unroll
            for (int i = 0; i < 3; i++) {
                int kg = k0n + ka[i];
                pa[i] = (kg < K5) ? g_g[(size_t)(m0 + ra[i]) * K5 + kg] : 0.f;
            }
            #pragma unroll
            for (int i = 0; i < 6; i++) {
                int kg = k0n + kb[i];
                pb[i] = (kg < K5) ? wih0[(size_t)(n0 + rb[i]) * K5 + kg] : 0.f;
            }
        }
        #pragma unroll
        for (int kk = 0; kk < KC; kk += 2) {
            unsigned long long av[3], bv[6];
            #pragma unroll
            for (int i = 0; i < 3; i++)
                av[i] = *(const unsigned long long*)&a_sm[(ty * 3 + i) * 18 + kk];
            #pragma unroll
            for (int j = 0; j < 6; j++)
                bv[j] = *(const unsigned long long*)&b_sm[(tx * 6 + j) * 18 + kk];
            #pragma unroll
            for (int i = 0; i < 3; i++)
                #pragma unroll
                for (int j = 0; j < 6; j++)
                    FFMA2(acc[i][j], av[i], bv[j]);
        }
        __syncthreads();
    }
    #pragma unroll
    for (int i = 0; i < 3; i++)
        #pragma unroll
        for (int j = 0; j < 6; j++) {
            int m = m0 + ty * 3 + i;
            int n = n0 + tx * 6 + j;
            g_gi0[(size_t)m * G3 + n] = hsum2(acc[i][j]) + bih0[n];
        }
}

// ---------------- GRU step pieces ----------------
// smem layout (floats): s_h[32*514] then s_w (up to 32*512)
#define HPAD 514

__device__ void gru_update(const float* __restrict__ gi,   // [B][1536] (bias included)
                           const float* __restrict__ hin,  // [B][512]
                           float* __restrict__ hout,       // [B][512]
                           float* __restrict__ outcopy,    // [B][512]
                           const float* __restrict__ whh,  // [1536][512]
                           const float* __restrict__ bhh,  // [1536]
                           int jtile, float* sm) {
    float* s_h = sm;                 // [32][514]
    float* s_w = sm + BATCH * HPAD;  // [24][512]
    int tid = threadIdx.x;
    for (int e = tid; e < BATCH * HID; e += 256) {
        int b = e >> 9, kk = e & 511;
        s_h[b * HPAD + kk] = hin[e];
    }
    for (int e = tid; e < 3 * 8 * HID; e += 256) {
        int r = e >> 9, kk = e & 511;
        int g = r >> 3, jl = r & 7;
        s_w[r * HID + kk] = whh[((size_t)(g * HID + jtile * 8 + jl)) * HID + kk];
    }
    __syncthreads();
    int b = tid & 31, jl = tid >> 5;
    const unsigned long long* hp = (const unsigned long long*)(s_h + b * HPAD);
    const unsigned long long* wr = (const unsigned long long*)(s_w + (0 * 8 + jl) * HID);
    const unsigned long long* wz = (const unsigned long long*)(s_w + (1 * 8 + jl) * HID);
    const unsigned long long* wn = (const unsigned long long*)(s_w + (2 * 8 + jl) * HID);
    unsigned long long ar = 0ull, az = 0ull, an = 0ull;
    #pragma unroll 8
    for (int q = 0; q < HID / 2; q++) {
        unsigned long long h2 = hp[q];
        FFMA2(ar, h2, wr[q]);
        FFMA2(az, h2, wz[q]);
        FFMA2(an, h2, wn[q]);
    }
    int j = jtile * 8 + jl;
    float ghr = hsum2(ar) + bhh[j];
    float ghz = hsum2(az) + bhh[HID + j];
    float ghn = hsum2(an) + bhh[2 * HID + j];
    float gir = gi[b * G3 + j];
    float giz = gi[b * G3 + HID + j];
    float gin = gi[b * G3 + 2 * HID + j];
    float r = 1.f / (1.f + expf(-(gir + ghr)));
    float z = 1.f / (1.f + expf(-(giz + ghz)));
    float n = tanhf(gin + r * ghn);
    float hprev = s_h[b * HPAD + j];
    float hnew = (1.f - z) * n + z * hprev;
    hout[b * HID + j] = hnew;
    outcopy[b * HID + j] = hnew;
}

__device__ void gemm_gi1(const float* __restrict__ inp,  // out1[t] [32][512]
                         const float* __restrict__ wih,  // [1536][512]
                         const float* __restrict__ bih,  // [1536]
                         float* __restrict__ gi1,        // [32][1536]
                         int ctile, float* sm) {
    float* s_in = sm;
    float* s_w = sm + BATCH * HPAD;   // [32][512]
    int tid = threadIdx.x;
    for (int e = tid; e < BATCH * HID; e += 256) {
        int b = e >> 9, kk = e & 511;
        s_in[b * HPAD + kk] = inp[e];
    }
    for (int e = tid; e < 32 * HID; e += 256) {
        int r = e >> 9, kk = e & 511;
        s_w[e] = wih[((size_t)(ctile * 32 + r)) * HID + kk];
    }
    __syncthreads();
    int b = tid & 31, cg = tid >> 5;  // cg 0..7, 4 cols each
    const unsigned long long* ip = (const unsigned long long*)(s_in + b * HPAD);
    unsigned long long acc0 = 0ull, acc1 = 0ull, acc2 = 0ull, acc3 = 0ull;
    const unsigned long long* w0 = (const unsigned long long*)(s_w + (cg * 4 + 0) * HID);
    const unsigned long long* w1 = (const unsigned long long*)(s_w + (cg * 4 + 1) * HID);
    const unsigned long long* w2 = (const unsigned long long*)(s_w + (cg * 4 + 2) * HID);
    const unsigned long long* w3 = (const unsigned long long*)(s_w + (cg * 4 + 3) * HID);
    #pragma unroll 8
    for (int q = 0; q < HID / 2; q++) {
        unsigned long long h2 = ip[q];
        FFMA2(acc0, h2, w0[q]);
        FFMA2(acc1, h2, w1[q]);
        FFMA2(acc2, h2, w2[q]);
        FFMA2(acc3, h2, w3[q]);
    }
    int col = ctile * 32 + cg * 4;
    gi1[b * G3 + col + 0] = hsum2(acc0) + bih[col + 0];
    gi1[b * G3 + col + 1] = hsum2(acc1) + bih[col + 1];
    gi1[b * G3 + col + 2] = hsum2(acc2) + bih[col + 2];
    gi1[b * G3 + col + 3] = hsum2(acc3) + bih[col + 3];
}

// pipelined step kernel: k in [0, S+1]
//   CTAs [0,64):    layer0 step k        (valid k < S)
//   CTAs [64,128):  layer1 step k-2      (valid 0 <= k-2 < S)
//   CTAs [128,176): gi1 GEMM for step k-1 (valid 0 <= k-1 < S)
__global__ __launch_bounds__(256) void gru_step_kernel(
        int k,
        const float* __restrict__ w_hh0, const float* __restrict__ b_hh0,
        const float* __restrict__ w_ih1, const float* __restrict__ b_ih1,
        const float* __restrict__ w_hh1, const float* __restrict__ b_hh1,
        float* __restrict__ d_out) {
    extern __shared__ float sm[];
    int cta = blockIdx.x;
    if (cta < 64) {
        if (k >= S) return;
        gru_update(g_gi0 + (size_t)k * BATCH * G3, g_h0[k & 1], g_h0[(k + 1) & 1],
                   g_out1 + (size_t)k * BATCH * HID, w_hh0, b_hh0, cta, sm);
    } else if (cta < 128) {
        int t = k - 2;
        if (t < 0 || t >= S) return;
        gru_update(g_gi1[t & 1], g_h1[t & 1], g_h1[(t + 1) & 1],
                   d_out + (size_t)t * BATCH * HID, w_hh1, b_hh1, cta - 64, sm);
    } else {
        int t = k - 1;
        if (t < 0 || t >= S) return;
        gemm_gi1(g_out1 + (size_t)t * BATCH * HID, w_ih1, b_ih1, g_gi1[t & 1],
                 cta - 128, sm);
    }
}

__global__ void copy_hn_kernel(float* __restrict__ d_out) {
    int i = blockIdx.x * blockDim.x + threadIdx.x;
    if (i < BATCH * HID) {
        // final states live in buffer parity ((S-1)+1)&1 = 1
        d_out[S * BATCH * HID + i] = g_h0[1][i];
        d_out[S * BATCH * HID + BATCH * HID + i] = g_h1[1][i];
    }
}

// ---------------- host launch ----------------
extern "C" void kernel_launch(void* const* d_in, const int* in_sizes, int n_in,
                              void* d_out, int out_size) {
    const float* x     = (const float*)d_in[0];
    const int*   ei    = (const int*)d_in[1];   // int32 or int64, detected on device
    const float* W1    = (const float*)d_in[2];
    const float* b1    = (const float*)d_in[3];
    const float* W2    = (const float*)d_in[4];
    const float* b2    = (const float*)d_in[5];
    const float* w_ih0 = (const float*)d_in[6];
    const float* w_hh0 = (const float*)d_in[7];
    const float* b_ih0 = (const float*)d_in[8];
    const float* b_hh0 = (const float*)d_in[9];
    const float* w_ih1 = (const float*)d_in[10];
    const float* w_hh1 = (const float*)d_in[11];
    const float* b_ih1 = (const float*)d_in[12];
    const float* b_hh1 = (const float*)d_in[13];
    float* out = (float*)d_out;

    const int SMEM_GCN  = 2 * 2 * NNODE * (int)sizeof(float);              // 80000
    const int SMEM_STEP = (BATCH * HPAD + 32 * HID) * (int)sizeof(float);  // 131328

    cudaFuncSetAttribute(gcn_kernel, cudaFuncAttributeMaxDynamicSharedMemorySize, SMEM_GCN);
    cudaFuncSetAttribute(gru_step_kernel, cudaFuncAttributeMaxDynamicSharedMemorySize, SMEM_STEP);

    init_kernel<<<(BATCH * HID + 255) / 256, 256>>>(ei);
    count_kernel<<<(NEDGE + 255) / 256, 256>>>(ei);
    scan_kernel<<<1, 1024>>>();
    fill_kernel<<<(NEDGE_SL + 255) / 256, 256>>>(ei);

    gcn_kernel<<<SB, 512, SMEM_GCN>>>(x, W1, b1, W2, b2);
    gemm_gi0_kernel<<<dim3(SB / BM, G3 / BN), 256>>>(w_ih0, b_ih0);

    for (int k = 0; k < S + 2; k++)
        gru_step_kernel<<<176, 256, SMEM_STEP>>>(k, w_hh0, b_hh0, w_ih1, b_ih1,
                                                 w_hh1, b_hh1, out);

    copy_hn_kernel<<<(BATCH * HID + 255) / 256, 256>>>(out);
}